// round 4
// baseline (speedup 1.0000x reference)
#include <cuda_runtime.h>

#define BB 8
#define TT 1024
#define CC 768
#define HH 12
#define HS 64
#define BT (BB*TT)
#define NQKV (3*CC)

// Scratch (allocation-free rule: __device__ globals)
__device__ float g_q[(size_t)BB*HH*TT*HS];
__device__ float g_k[(size_t)BB*HH*TT*HS];
__device__ float g_v[(size_t)BB*HH*TT*HS];
__device__ float g_att[(size_t)BB*TT*CC];

// ---------------------------------------------------------------------------
// Kernel 1: fused QKV projection.  out[(b,h,t,d)] = sum_c x[b,t,c]*W[h,c,d]
// Treated as GEMM [8192,768] x [768,2304]; each 64-wide n-tile maps to one
// (which, head) pair since 64 | 768.
// ---------------------------------------------------------------------------
__global__ __launch_bounds__(128) void qkv_gemm(
    const float* __restrict__ x,
    const float* __restrict__ Wq,
    const float* __restrict__ Wk,
    const float* __restrict__ Wv)
{
    __shared__ float As[64][17];   // [m][k], padded
    __shared__ float Bs[16][64];   // [k][n]

    const int tid = threadIdx.x;
    const int tx = tid & 15;       // n-frag index (0..15)
    const int ty = tid >> 4;       // m-frag index (0..7)
    const int colBase = blockIdx.x * 64;   // 0..2303
    const int rowBase = blockIdx.y * 64;   // 0..8191

    const int which = colBase / CC;            // 0=q 1=k 2=v
    const int h     = (colBase % CC) / HS;     // head
    const float* W = (which == 0 ? Wq : (which == 1 ? Wk : Wv)) + (size_t)h * CC * HS;

    float acc[8][4];
    #pragma unroll
    for (int i = 0; i < 8; i++)
        #pragma unroll
        for (int j = 0; j < 4; j++) acc[i][j] = 0.f;

    for (int k0 = 0; k0 < CC; k0 += 16) {
        #pragma unroll
        for (int i = 0; i < 8; i++) {
            int idx = tid + i * 128;
            int r = idx >> 4, c = idx & 15;
            As[r][c] = x[(size_t)(rowBase + r) * CC + k0 + c];
        }
        #pragma unroll
        for (int i = 0; i < 8; i++) {
            int idx = tid + i * 128;
            int r = idx >> 6, c = idx & 63;
            Bs[r][c] = W[(size_t)(k0 + r) * HS + c];
        }
        __syncthreads();

        #pragma unroll
        for (int kk = 0; kk < 16; kk++) {
            float4 b4 = *reinterpret_cast<const float4*>(&Bs[kk][tx * 4]);
            float bb[4] = {b4.x, b4.y, b4.z, b4.w};
            #pragma unroll
            for (int i = 0; i < 8; i++) {
                float a = As[ty * 8 + i][kk];
                #pragma unroll
                for (int j = 0; j < 4; j++)
                    acc[i][j] = fmaf(a, bb[j], acc[i][j]);
            }
        }
        __syncthreads();
    }

    float* dst = (which == 0 ? g_q : (which == 1 ? g_k : g_v));
    #pragma unroll
    for (int i = 0; i < 8; i++) {
        int m = rowBase + ty * 8 + i;
        int b = m >> 10;
        int t = m & 1023;
        size_t base = (((size_t)b * HH + h) * TT + t) * HS;
        #pragma unroll
        for (int j = 0; j < 4; j++)
            dst[base + tx * 4 + j] = acc[i][j];
    }
}

// ---------------------------------------------------------------------------
// Kernel 2: causal flash attention, fp32 online softmax.
// grid = (16 q-tiles, 96 bh). block = 128 threads = 64 rows x 2 half-threads.
// Each half-thread owns the full 64-dim q row (registers), 32 interleaved
// j-columns of S and 32 interleaved d-columns of the accumulator.
// P values are exchanged between the row pair via shfl_xor (no S smem tile).
// ---------------------------------------------------------------------------
__global__ __launch_bounds__(128) void attn_kernel()
{
    __shared__ float Ks[64 * 65];  // [j][d] padded
    __shared__ float Vs[64 * 64];  // [j][d] unpadded (interleaved-d access)

    const int tid  = threadIdx.x;
    const int r    = tid >> 1;     // q row within tile (0..63)
    const int half = tid & 1;      // 0/1
    const int qt   = blockIdx.x;   // q tile (0..15)
    const int bh   = blockIdx.y;   // 0..95

    const float scale = 0.125f;    // 1/sqrt(64)
    const float* Qb = g_q + (size_t)bh * TT * HS + (size_t)qt * 64 * HS;
    const float* Kb = g_k + (size_t)bh * TT * HS;
    const float* Vb = g_v + (size_t)bh * TT * HS;
    const int trow = qt * 64 + r;

    float q[64];
    #pragma unroll
    for (int d = 0; d < 64; d++) q[d] = Qb[r * 64 + d] * scale;

    float mrow = -1e30f, lrow = 0.f;
    float acc[32];
    #pragma unroll
    for (int d = 0; d < 32; d++) acc[d] = 0.f;

    for (int kt = 0; kt <= qt; kt++) {
        __syncthreads();  // protect Ks/Vs from previous-iteration readers
        const float* Kt = Kb + (size_t)kt * 64 * HS;
        const float* Vt = Vb + (size_t)kt * 64 * HS;
        #pragma unroll
        for (int i = 0; i < 32; i++) {
            int idx = tid + i * 128;
            int rr = idx >> 6, dd = idx & 63;
            Ks[rr * 65 + dd] = Kt[idx];
            Vs[rr * 64 + dd] = Vt[idx];
        }
        __syncthreads();

        const bool diag = (kt == qt);
        float s[32];
        float tmax = -1e30f;
        #pragma unroll
        for (int jj = 0; jj < 32; jj++) {
            int j = 2 * jj + half;
            const float* kr = &Ks[j * 65];
            float sum = 0.f;
            #pragma unroll
            for (int d = 0; d < 64; d++) sum = fmaf(q[d], kr[d], sum);
            if (diag && (kt * 64 + j) > trow) sum = -1e30f;
            s[jj] = sum;
            tmax = fmaxf(tmax, sum);
        }
        tmax = fmaxf(tmax, __shfl_xor_sync(0xffffffffu, tmax, 1));
        float mnew = fmaxf(mrow, tmax);
        float corr = __expf(mrow - mnew);
        float lsum = 0.f;
        #pragma unroll
        for (int jj = 0; jj < 32; jj++) {
            float p = __expf(s[jj] - mnew);
            s[jj] = p;
            lsum += p;
        }
        lsum += __shfl_xor_sync(0xffffffffu, lsum, 1);
        lrow = lrow * corr + lsum;
        mrow = mnew;

        #pragma unroll
        for (int d = 0; d < 32; d++) acc[d] *= corr;

        #pragma unroll
        for (int jj = 0; jj < 32; jj++) {
            float pown = s[jj];
            float poth = __shfl_xor_sync(0xffffffffu, pown, 1);
            float pe = half ? poth : pown;  // p for j = 2jj
            float po = half ? pown : poth;  // p for j = 2jj+1
            const float* v0 = &Vs[(2 * jj) * 64 + half];
            const float* v1 = &Vs[(2 * jj + 1) * 64 + half];
            #pragma unroll
            for (int d = 0; d < 32; d++) {
                acc[d] = fmaf(pe, v0[2 * d], acc[d]);
                acc[d] = fmaf(po, v1[2 * d], acc[d]);
            }
        }
    }

    float inv = 1.0f / lrow;
    int b = bh / HH, h = bh % HH;
    float* outp = g_att + ((size_t)b * TT + trow) * CC + h * 64;
    #pragma unroll
    for (int d = 0; d < 32; d++)
        outp[2 * d + half] = acc[d] * inv;
}

// ---------------------------------------------------------------------------
// Kernel 3: output projection.  out[i][j] = sum_c att[i][c]*Wproj[j][c] + b[j]
// ---------------------------------------------------------------------------
__global__ __launch_bounds__(128) void proj_gemm(
    const float* __restrict__ Wp,
    const float* __restrict__ bp,
    float* __restrict__ out)
{
    __shared__ float As[64][17];   // [m][k]
    __shared__ float Bs[64][17];   // [n][k] (Wproj rows are n)

    const int tid = threadIdx.x;
    const int tx = tid & 15;
    const int ty = tid >> 4;
    const int colBase = blockIdx.x * 64;   // 0..767
    const int rowBase = blockIdx.y * 64;   // 0..8191

    float acc[8][4];
    #pragma unroll
    for (int i = 0; i < 8; i++)
        #pragma unroll
        for (int j = 0; j < 4; j++) acc[i][j] = 0.f;

    for (int k0 = 0; k0 < CC; k0 += 16) {
        #pragma unroll
        for (int i = 0; i < 8; i++) {
            int idx = tid + i * 128;
            int r = idx >> 4, c = idx & 15;
            As[r][c] = g_att[(size_t)(rowBase + r) * CC + k0 + c];
            Bs[r][c] = Wp[(size_t)(colBase + r) * CC + k0 + c];
        }
        __syncthreads();

        #pragma unroll
        for (int kk = 0; kk < 16; kk++) {
            float a[8], bb[4];
            #pragma unroll
            for (int i = 0; i < 8; i++) a[i] = As[ty * 8 + i][kk];
            #pragma unroll
            for (int j = 0; j < 4; j++) bb[j] = Bs[tx * 4 + j][kk];
            #pragma unroll
            for (int i = 0; i < 8; i++)
                #pragma unroll
                for (int j = 0; j < 4; j++)
                    acc[i][j] = fmaf(a[i], bb[j], acc[i][j]);
        }
        __syncthreads();
    }

    #pragma unroll
    for (int j = 0; j < 4; j++) {
        float bias = bp[colBase + tx * 4 + j];
        #pragma unroll
        for (int i = 0; i < 8; i++) {
            int mrow = rowBase + ty * 8 + i;
            out[(size_t)mrow * CC + colBase + tx * 4 + j] = acc[i][j] + bias;
        }
    }
}

// ---------------------------------------------------------------------------
extern "C" void kernel_launch(void* const* d_in, const int* in_sizes, int n_in,
                              void* d_out, int out_size)
{
    const float* x  = (const float*)d_in[0];
    const float* Wq = (const float*)d_in[1];
    const float* Wk = (const float*)d_in[2];
    const float* Wv = (const float*)d_in[3];
    const float* Wp = (const float*)d_in[4];
    const float* bp = (const float*)d_in[5];
    float* out = (float*)d_out;

    qkv_gemm<<<dim3(NQKV / 64, BT / 64), 128>>>(x, Wq, Wk, Wv);
    attn_kernel<<<dim3(TT / 64, BB * HH), 128>>>();
    proj_gemm<<<dim3(CC / 64, BT / 64), 128>>>(Wp, bp, out);
}

// round 7
// speedup vs baseline: 1.5123x; 1.5123x over previous
#include <cuda_runtime.h>

#define BB 8
#define TT 1024
#define CC 768
#define HH 12
#define HS 64
#define BT (BB*TT)
#define NQKV (3*CC)

// Scratch (allocation-free rule: __device__ globals)
__device__ float g_q[(size_t)BB*HH*TT*HS];
__device__ float g_k[(size_t)BB*HH*TT*HS];
__device__ float g_v[(size_t)BB*HH*TT*HS];
__device__ float g_att[(size_t)BB*TT*CC];

// ---------------------------------------------------------------------------
// Kernel 1: fused QKV projection. GEMM [8192,768] x [768,2304].
// 128(m) x 64(n) tiles, 128 threads, 8x8 register fragments.
// As stored k-major so both fragments load as float4 (4 LDS.128 / 64 FMA).
// ---------------------------------------------------------------------------
__global__ __launch_bounds__(128) void qkv_gemm(
    const float* __restrict__ x,
    const float* __restrict__ Wq,
    const float* __restrict__ Wk,
    const float* __restrict__ Wv)
{
    __shared__ float As[16][132];  // [k][m], pad 132 (16B-aligned rows)
    __shared__ float Bs[16][68];   // [k][n]

    const int tid = threadIdx.x;
    const int tx = tid & 7;        // n-frag group (cols tx*4 and 32+tx*4)
    const int ty = tid >> 3;       // m-frag group (rows ty*8 .. +7)
    const int colBase = blockIdx.x * 64;    // 0..2303
    const int rowBase = blockIdx.y * 128;   // 0..8191

    const int which = colBase / CC;            // 0=q 1=k 2=v
    const int h     = (colBase % CC) / HS;     // head
    const float* W = (which == 0 ? Wq : (which == 1 ? Wk : Wv)) + (size_t)h * CC * HS;

    float acc[8][8];
    #pragma unroll
    for (int i = 0; i < 8; i++)
        #pragma unroll
        for (int j = 0; j < 8; j++) acc[i][j] = 0.f;

    for (int k0 = 0; k0 < CC; k0 += 16) {
        #pragma unroll
        for (int i = 0; i < 16; i++) {
            int idx = tid + i * 128;
            int r = idx >> 4, c = idx & 15;
            As[c][r] = x[(size_t)(rowBase + r) * CC + k0 + c];
        }
        #pragma unroll
        for (int i = 0; i < 8; i++) {
            int idx = tid + i * 128;
            int r = idx >> 6, c = idx & 63;
            Bs[r][c] = W[(size_t)(k0 + r) * HS + c];
        }
        __syncthreads();

        #pragma unroll
        for (int kk = 0; kk < 16; kk++) {
            float4 a0 = *reinterpret_cast<const float4*>(&As[kk][ty * 8]);
            float4 a1 = *reinterpret_cast<const float4*>(&As[kk][ty * 8 + 4]);
            float4 b0 = *reinterpret_cast<const float4*>(&Bs[kk][tx * 4]);
            float4 b1 = *reinterpret_cast<const float4*>(&Bs[kk][32 + tx * 4]);
            float a[8] = {a0.x, a0.y, a0.z, a0.w, a1.x, a1.y, a1.z, a1.w};
            float b[8] = {b0.x, b0.y, b0.z, b0.w, b1.x, b1.y, b1.z, b1.w};
            #pragma unroll
            for (int i = 0; i < 8; i++)
                #pragma unroll
                for (int j = 0; j < 8; j++)
                    acc[i][j] = fmaf(a[i], b[j], acc[i][j]);
        }
        __syncthreads();
    }

    float* dst = (which == 0 ? g_q : (which == 1 ? g_k : g_v));
    #pragma unroll
    for (int i = 0; i < 8; i++) {
        int m = rowBase + ty * 8 + i;
        int b = m >> 10;
        int t = m & 1023;
        size_t base = (((size_t)b * HH + h) * TT + t) * HS;
        float4 lo = make_float4(acc[i][0], acc[i][1], acc[i][2], acc[i][3]);
        float4 hi = make_float4(acc[i][4], acc[i][5], acc[i][6], acc[i][7]);
        *reinterpret_cast<float4*>(&dst[base + tx * 4])      = lo;
        *reinterpret_cast<float4*>(&dst[base + 32 + tx * 4]) = hi;
    }
}

// ---------------------------------------------------------------------------
// Kernel 2: causal flash attention, fp32 online softmax.
// grid = (16 q-tiles, 96 bh). block = 128 threads = 64 rows x 2 half-threads.
// K/V tiles padded to 68 floats/row so all inner reads are LDS.128.
// Half-threads own float4-interleaved d-chunks of V/acc (adjacent bank groups).
// ---------------------------------------------------------------------------
__global__ __launch_bounds__(128) void attn_kernel()
{
    __shared__ float Ks[64 * 68];  // [j][d] padded, rows 16B-aligned
    __shared__ float Vs[64 * 68];

    const int tid  = threadIdx.x;
    const int r    = tid >> 1;     // q row within tile (0..63)
    const int half = tid & 1;      // 0/1
    const int qt   = blockIdx.x;   // q tile (0..15)
    const int bh   = blockIdx.y;   // 0..95

    const float scale = 0.125f;    // 1/sqrt(64)
    const float* Qb = g_q + (size_t)bh * TT * HS + (size_t)qt * 64 * HS;
    const float* Kb = g_k + (size_t)bh * TT * HS;
    const float* Vb = g_v + (size_t)bh * TT * HS;
    const int trow = qt * 64 + r;

    float q[64];
    {
        const float4* qp = reinterpret_cast<const float4*>(Qb + r * 64);
        #pragma unroll
        for (int i = 0; i < 16; i++) {
            float4 q4 = qp[i];
            q[4*i+0] = q4.x * scale;
            q[4*i+1] = q4.y * scale;
            q[4*i+2] = q4.z * scale;
            q[4*i+3] = q4.w * scale;
        }
    }

    float mrow = -1e30f, lrow = 0.f;
    float acc[32];
    #pragma unroll
    for (int d = 0; d < 32; d++) acc[d] = 0.f;

    for (int kt = 0; kt <= qt; kt++) {
        __syncthreads();  // protect Ks/Vs from previous-iteration readers
        const float* Kt = Kb + (size_t)kt * 64 * HS;
        const float* Vt = Vb + (size_t)kt * 64 * HS;
        #pragma unroll
        for (int i = 0; i < 32; i++) {
            int idx = tid + i * 128;
            int rr = idx >> 6, dd = idx & 63;
            Ks[rr * 68 + dd] = Kt[idx];
            Vs[rr * 68 + dd] = Vt[idx];
        }
        __syncthreads();

        const bool diag = (kt == qt);
        float s[32];
        float tmax = -1e30f;
        #pragma unroll
        for (int jj = 0; jj < 32; jj++) {
            int j = 2 * jj + half;
            const float4* kr = reinterpret_cast<const float4*>(&Ks[j * 68]);
            float sum = 0.f;
            #pragma unroll
            for (int i = 0; i < 16; i++) {
                float4 k4 = kr[i];
                sum = fmaf(q[4*i+0], k4.x, sum);
                sum = fmaf(q[4*i+1], k4.y, sum);
                sum = fmaf(q[4*i+2], k4.z, sum);
                sum = fmaf(q[4*i+3], k4.w, sum);
            }
            if (diag && (kt * 64 + j) > trow) sum = -1e30f;
            s[jj] = sum;
            tmax = fmaxf(tmax, sum);
        }
        tmax = fmaxf(tmax, __shfl_xor_sync(0xffffffffu, tmax, 1));
        float mnew = fmaxf(mrow, tmax);
        float corr = __expf(mrow - mnew);
        float lsum = 0.f;
        #pragma unroll
        for (int jj = 0; jj < 32; jj++) {
            float p = __expf(s[jj] - mnew);
            s[jj] = p;
            lsum += p;
        }
        lsum += __shfl_xor_sync(0xffffffffu, lsum, 1);
        lrow = lrow * corr + lsum;
        mrow = mnew;

        #pragma unroll
        for (int d = 0; d < 32; d++) acc[d] *= corr;

        #pragma unroll
        for (int jj = 0; jj < 32; jj++) {
            float pown = s[jj];
            float poth = __shfl_xor_sync(0xffffffffu, pown, 1);
            float pe = half ? poth : pown;  // p for j = 2jj
            float po = half ? pown : poth;  // p for j = 2jj+1
            const float* v0 = &Vs[(2 * jj) * 68];
            const float* v1 = &Vs[(2 * jj + 1) * 68];
            #pragma unroll
            for (int i = 0; i < 8; i++) {
                // this half owns d-chunk (2*i+half)*4 .. +3
                float4 a4 = *reinterpret_cast<const float4*>(&v0[(2 * i + half) * 4]);
                float4 b4 = *reinterpret_cast<const float4*>(&v1[(2 * i + half) * 4]);
                acc[4*i+0] = fmaf(pe, a4.x, acc[4*i+0]);
                acc[4*i+1] = fmaf(pe, a4.y, acc[4*i+1]);
                acc[4*i+2] = fmaf(pe, a4.z, acc[4*i+2]);
                acc[4*i+3] = fmaf(pe, a4.w, acc[4*i+3]);
                acc[4*i+0] = fmaf(po, b4.x, acc[4*i+0]);
                acc[4*i+1] = fmaf(po, b4.y, acc[4*i+1]);
                acc[4*i+2] = fmaf(po, b4.z, acc[4*i+2]);
                acc[4*i+3] = fmaf(po, b4.w, acc[4*i+3]);
            }
        }
    }

    float inv = 1.0f / lrow;
    int b = bh / HH, h = bh % HH;
    float* outp = g_att + ((size_t)b * TT + trow) * CC + h * 64;
    #pragma unroll
    for (int i = 0; i < 8; i++) {
        float4 o4 = make_float4(acc[4*i+0] * inv, acc[4*i+1] * inv,
                                acc[4*i+2] * inv, acc[4*i+3] * inv);
        *reinterpret_cast<float4*>(&outp[(2 * i + half) * 4]) = o4;
    }
}

// ---------------------------------------------------------------------------
// Kernel 3: output projection.  out[i][j] = sum_c att[i][c]*Wproj[j][c] + b[j]
// Same 128x64 / 8x8 tiling as qkv; Wproj rows (n) stored k-major in smem.
// ---------------------------------------------------------------------------
__global__ __launch_bounds__(128) void proj_gemm(
    const float* __restrict__ Wp,
    const float* __restrict__ bp,
    float* __restrict__ out)
{
    __shared__ float As[16][132];  // [k][m]
    __shared__ float Bs[16][68];   // [k][n]

    const int tid = threadIdx.x;
    const int tx = tid & 7;
    const int ty = tid >> 3;
    const int colBase = blockIdx.x * 64;    // 0..767
    const int rowBase = blockIdx.y * 128;   // 0..8191

    float acc[8][8];
    #pragma unroll
    for (int i = 0; i < 8; i++)
        #pragma unroll
        for (int j = 0; j < 8; j++) acc[i][j] = 0.f;

    for (int k0 = 0; k0 < CC; k0 += 16) {
        #pragma unroll
        for (int i = 0; i < 16; i++) {
            int idx = tid + i * 128;
            int r = idx >> 4, c = idx & 15;
            As[c][r] = g_att[(size_t)(rowBase + r) * CC + k0 + c];
        }
        #pragma unroll
        for (int i = 0; i < 8; i++) {
            int idx = tid + i * 128;
            int r = idx >> 4, c = idx & 15;  // r = n row (0..63), c = k
            Bs[c][r] = Wp[(size_t)(colBase + r) * CC + k0 + c];
        }
        __syncthreads();

        #pragma unroll
        for (int kk = 0; kk < 16; kk++) {
            float4 a0 = *reinterpret_cast<const float4*>(&As[kk][ty * 8]);
            float4 a1 = *reinterpret_cast<const float4*>(&As[kk][ty * 8 + 4]);
            float4 b0 = *reinterpret_cast<const float4*>(&Bs[kk][tx * 4]);
            float4 b1 = *reinterpret_cast<const float4*>(&Bs[kk][32 + tx * 4]);
            float a[8] = {a0.x, a0.y, a0.z, a0.w, a1.x, a1.y, a1.z, a1.w};
            float b[8] = {b0.x, b0.y, b0.z, b0.w, b1.x, b1.y, b1.z, b1.w};
            #pragma unroll
            for (int i = 0; i < 8; i++)
                #pragma unroll
                for (int j = 0; j < 8; j++)
                    acc[i][j] = fmaf(a[i], b[j], acc[i][j]);
        }
        __syncthreads();
    }

    float blo[4], bhi[4];
    #pragma unroll
    for (int j = 0; j < 4; j++) {
        blo[j] = bp[colBase + tx * 4 + j];
        bhi[j] = bp[colBase + 32 + tx * 4 + j];
    }
    #pragma unroll
    for (int i = 0; i < 8; i++) {
        int m = rowBase + ty * 8 + i;
        float4 lo = make_float4(acc[i][0] + blo[0], acc[i][1] + blo[1],
                                acc[i][2] + blo[2], acc[i][3] + blo[3]);
        float4 hi = make_float4(acc[i][4] + bhi[0], acc[i][5] + bhi[1],
                                acc[i][6] + bhi[2], acc[i][7] + bhi[3]);
        *reinterpret_cast<float4*>(&out[(size_t)m * CC + colBase + tx * 4])      = lo;
        *reinterpret_cast<float4*>(&out[(size_t)m * CC + colBase + 32 + tx * 4]) = hi;
    }
}

// ---------------------------------------------------------------------------
extern "C" void kernel_launch(void* const* d_in, const int* in_sizes, int n_in,
                              void* d_out, int out_size)
{
    const float* x  = (const float*)d_in[0];
    const float* Wq = (const float*)d_in[1];
    const float* Wk = (const float*)d_in[2];
    const float* Wv = (const float*)d_in[3];
    const float* Wp = (const float*)d_in[4];
    const float* bp = (const float*)d_in[5];
    float* out = (float*)d_out;

    qkv_gemm<<<dim3(NQKV / 64, BT / 128), 128>>>(x, Wq, Wk, Wv);
    attn_kernel<<<dim3(TT / 64, BB * HH), 128>>>();
    proj_gemm<<<dim3(CC / 64, BT / 128), 128>>>(Wp, bp, out);
}

// round 11
// speedup vs baseline: 2.2571x; 1.4925x over previous
#include <cuda_runtime.h>
#include <cstdint>

#define BB 8
#define TT 1024
#define CC 768
#define HH 12
#define HS 64
#define BT (BB*TT)
#define NQKV (3*CC)

// GEMM tiling
#define BM 128
#define BN 128
#define BK 16
#define LDT 36          // smem tile row stride (words): banks (4g+t)%32 all distinct

// Scratch (allocation-free rule: __device__ globals)
__device__ float g_qkv[(size_t)BT*NQKV];   // [m][n], n = which*768 + h*64 + d
__device__ float g_Bw[(size_t)NQKV*CC];    // K-major transposed QKV weights [n][k]
__device__ float g_att[(size_t)BT*CC];

__device__ __forceinline__ uint32_t f2tf(float f){
    uint32_t r; asm("cvt.rna.tf32.f32 %0, %1;" : "=r"(r) : "f"(f)); return r;
}

__device__ __forceinline__ void mma_tf32(float* d, const uint32_t* a, const uint32_t* b){
    asm volatile(
        "mma.sync.aligned.m16n8k8.row.col.f32.tf32.tf32.f32 "
        "{%0,%1,%2,%3}, {%4,%5,%6,%7}, {%8,%9}, {%0,%1,%2,%3};"
        : "+f"(d[0]), "+f"(d[1]), "+f"(d[2]), "+f"(d[3])
        : "r"(a[0]), "r"(a[1]), "r"(a[2]), "r"(a[3]), "r"(b[0]), "r"(b[1]));
}

// ---------------------------------------------------------------------------
// Kernel 0: tiled transpose of QKV weights into K-major g_Bw[n][k].
// n = which*768 + h*64 + d ; g_Bw[n][k] = W_which[h][k][d].
// grid (12 k-tiles, 12 heads, 3 which), block 256. Coalesced both sides.
// ---------------------------------------------------------------------------
__global__ __launch_bounds__(256) void prep_w(const float* __restrict__ Wq,
                                              const float* __restrict__ Wk,
                                              const float* __restrict__ Wv)
{
    __shared__ float Ts[64][65];
    const int kt = blockIdx.x, h = blockIdx.y, which = blockIdx.z;
    const int tid = threadIdx.x;
    const float* W = (which == 0 ? Wq : (which == 1 ? Wk : Wv));

    #pragma unroll
    for (int i = 0; i < 16; i++) {
        int idx = tid + i * 256;
        int kk = idx >> 6, d = idx & 63;
        Ts[kk][d] = W[((size_t)h * CC + kt * 64 + kk) * HS + d];
    }
    __syncthreads();
    #pragma unroll
    for (int i = 0; i < 16; i++) {
        int idx = tid + i * 256;
        int d = idx >> 6, kk = idx & 63;
        g_Bw[((size_t)which * CC + h * 64 + d) * CC + kt * 64 + kk] = Ts[kk][d];
    }
}

// ---------------------------------------------------------------------------
// Kernels 1+3: tf32 mma.sync GEMM  D[M][N] = A[M][768] * B[N][768]^T (+bias)
// mode 0: A=x, B=g_Bw, out=g_qkv (ldc=2304), no bias
// mode 1: A=g_att, B=Wp, out=d_out (ldc=768), +bias
// 128x128x16 tiles, 256 thr = 8 warps (2m x 4n), warp tile 64x32 (4x4 m16n8).
// ---------------------------------------------------------------------------
__global__ __launch_bounds__(256) void gemm_mma(
    const float* __restrict__ Aext,
    const float* __restrict__ Bext,
    float* __restrict__ outext,
    const float* __restrict__ bias,
    int ldc, int mode)
{
    __shared__ uint32_t As[BM * LDT];   // [m][k] tf32 bits, pad 36
    __shared__ uint32_t Bs[BN * LDT];   // [n][k]

    const float* A   = mode ? g_att : Aext;
    const float* Bm  = mode ? Bext  : g_Bw;
    float*       out = mode ? outext : g_qkv;

    const int tid  = threadIdx.x;
    const int wid  = tid >> 5, lane = tid & 31;
    const int g    = lane >> 2, t = lane & 3;
    const int wm   = wid & 1;          // 0..1  (64-row m slab)
    const int wn   = wid >> 1;         // 0..3  (32-col n slab)
    const int rowBase = blockIdx.y * BM;
    const int colBase = blockIdx.x * BN;

    // staging indices: each thread 2 float4 per operand; lanes cover k first
    const int sm = tid >> 2;           // 0..63  (+64 for i=1)
    const int sk = (tid & 3) * 4;      // 0,4,8,12

    float acc[4][4][4];
    #pragma unroll
    for (int i = 0; i < 4; i++)
        #pragma unroll
        for (int j = 0; j < 4; j++)
            #pragma unroll
            for (int c = 0; c < 4; c++) acc[i][j][c] = 0.f;

    for (int k0 = 0; k0 < CC; k0 += BK) {
        // gmem -> regs (coalesced 64B rows), convert to tf32
        uint4 ar[2], br[2];
        #pragma unroll
        for (int i = 0; i < 2; i++) {
            float4 av = *reinterpret_cast<const float4*>(
                &A[(size_t)(rowBase + sm + i * 64) * CC + k0 + sk]);
            float4 bv = *reinterpret_cast<const float4*>(
                &Bm[(size_t)(colBase + sm + i * 64) * CC + k0 + sk]);
            ar[i] = make_uint4(f2tf(av.x), f2tf(av.y), f2tf(av.z), f2tf(av.w));
            br[i] = make_uint4(f2tf(bv.x), f2tf(bv.y), f2tf(bv.z), f2tf(bv.w));
        }
        __syncthreads();   // previous iter's fragment readers done
        #pragma unroll
        for (int i = 0; i < 2; i++) {
            *reinterpret_cast<uint4*>(&As[(sm + i * 64) * LDT + sk]) = ar[i];
            *reinterpret_cast<uint4*>(&Bs[(sm + i * 64) * LDT + sk]) = br[i];
        }
        __syncthreads();

        #pragma unroll
        for (int kk = 0; kk < BK; kk += 8) {
            uint32_t af[4][4], bf[4][2];
            #pragma unroll
            for (int mi = 0; mi < 4; mi++) {
                const uint32_t* p = &As[(wm * 64 + mi * 16 + g) * LDT + kk + t];
                af[mi][0] = p[0];
                af[mi][1] = p[8 * LDT];
                af[mi][2] = p[4];
                af[mi][3] = p[8 * LDT + 4];
            }
            #pragma unroll
            for (int ni = 0; ni < 4; ni++) {
                const uint32_t* p = &Bs[(wn * 32 + ni * 8 + g) * LDT + kk + t];
                bf[ni][0] = p[0];
                bf[ni][1] = p[4];
            }
            #pragma unroll
            for (int mi = 0; mi < 4; mi++)
                #pragma unroll
                for (int ni = 0; ni < 4; ni++)
                    mma_tf32(acc[mi][ni], af[mi], bf[ni]);
        }
    }

    // epilogue: c0/c1 at (row g, cols 2t,2t+1), c2/c3 at row g+8
    #pragma unroll
    for (int mi = 0; mi < 4; mi++) {
        int r0 = rowBase + wm * 64 + mi * 16 + g;
        #pragma unroll
        for (int ni = 0; ni < 4; ni++) {
            int c = colBase + wn * 32 + ni * 8 + 2 * t;
            float b0 = 0.f, b1 = 0.f;
            if (bias) { b0 = bias[c]; b1 = bias[c + 1]; }
            float2 lo = make_float2(acc[mi][ni][0] + b0, acc[mi][ni][1] + b1);
            float2 hi = make_float2(acc[mi][ni][2] + b0, acc[mi][ni][3] + b1);
            *reinterpret_cast<float2*>(&out[(size_t)r0 * ldc + c])       = lo;
            *reinterpret_cast<float2*>(&out[(size_t)(r0 + 8) * ldc + c]) = hi;
        }
    }
}

// ---------------------------------------------------------------------------
// Kernel 2: causal flash attention, fp32 online softmax,
// reading q/k/v from fused g_qkv[m][2304] layout.
// ---------------------------------------------------------------------------
__global__ __launch_bounds__(128) void attn_kernel()
{
    __shared__ float Ks[64 * 68];
    __shared__ float Vs[64 * 68];

    const int tid  = threadIdx.x;
    const int r    = tid >> 1;
    const int half = tid & 1;
    const int qt   = blockIdx.x;
    const int bh   = blockIdx.y;
    const int b = bh / HH, h = bh % HH;

    const float scale = 0.125f;
    const size_t m0 = (size_t)b * TT;
    const int trow = qt * 64 + r;

    float q[64];
    {
        const float4* qp = reinterpret_cast<const float4*>(
            g_qkv + (m0 + trow) * NQKV + h * HS);
        #pragma unroll
        for (int i = 0; i < 16; i++) {
            float4 q4 = qp[i];
            q[4*i+0] = q4.x * scale;
            q[4*i+1] = q4.y * scale;
            q[4*i+2] = q4.z * scale;
            q[4*i+3] = q4.w * scale;
        }
    }

    float mrow = -1e30f, lrow = 0.f;
    float acc[32];
    #pragma unroll
    for (int d = 0; d < 32; d++) acc[d] = 0.f;

    for (int kt = 0; kt <= qt; kt++) {
        __syncthreads();
        const float* Kt = g_qkv + (m0 + (size_t)kt * 64) * NQKV + CC + h * HS;
        const float* Vt = g_qkv + (m0 + (size_t)kt * 64) * NQKV + 2 * CC + h * HS;
        #pragma unroll
        for (int i = 0; i < 8; i++) {
            int idx = tid + i * 128;
            int rr = idx >> 4, d4 = idx & 15;
            float4 kv = *reinterpret_cast<const float4*>(Kt + (size_t)rr * NQKV + d4 * 4);
            float4 vv = *reinterpret_cast<const float4*>(Vt + (size_t)rr * NQKV + d4 * 4);
            *reinterpret_cast<float4*>(&Ks[rr * 68 + d4 * 4]) = kv;
            *reinterpret_cast<float4*>(&Vs[rr * 68 + d4 * 4]) = vv;
        }
        __syncthreads();

        const bool diag = (kt == qt);
        float s[32];
        float tmax = -1e30f;
        #pragma unroll
        for (int jj = 0; jj < 32; jj++) {
            int j = 2 * jj + half;
            const float4* kr = reinterpret_cast<const float4*>(&Ks[j * 68]);
            float sum = 0.f;
            #pragma unroll
            for (int i = 0; i < 16; i++) {
                float4 k4 = kr[i];
                sum = fmaf(q[4*i+0], k4.x, sum);
                sum = fmaf(q[4*i+1], k4.y, sum);
                sum = fmaf(q[4*i+2], k4.z, sum);
                sum = fmaf(q[4*i+3], k4.w, sum);
            }
            if (diag && (kt * 64 + j) > trow) sum = -1e30f;
            s[jj] = sum;
            tmax = fmaxf(tmax, sum);
        }
        tmax = fmaxf(tmax, __shfl_xor_sync(0xffffffffu, tmax, 1));
        float mnew = fmaxf(mrow, tmax);
        float corr = __expf(mrow - mnew);
        float lsum = 0.f;
        #pragma unroll
        for (int jj = 0; jj < 32; jj++) {
            float p = __expf(s[jj] - mnew);
            s[jj] = p;
            lsum += p;
        }
        lsum += __shfl_xor_sync(0xffffffffu, lsum, 1);
        lrow = lrow * corr + lsum;
        mrow = mnew;

        #pragma unroll
        for (int d = 0; d < 32; d++) acc[d] *= corr;

        #pragma unroll
        for (int jj = 0; jj < 32; jj++) {
            float pown = s[jj];
            float poth = __shfl_xor_sync(0xffffffffu, pown, 1);
            float pe = half ? poth : pown;
            float po = half ? pown : poth;
            const float* v0 = &Vs[(2 * jj) * 68];
            const float* v1 = &Vs[(2 * jj + 1) * 68];
            #pragma unroll
            for (int i = 0; i < 8; i++) {
                float4 a4 = *reinterpret_cast<const float4*>(&v0[(2 * i + half) * 4]);
                float4 b4 = *reinterpret_cast<const float4*>(&v1[(2 * i + half) * 4]);
                acc[4*i+0] = fmaf(pe, a4.x, acc[4*i+0]);
                acc[4*i+1] = fmaf(pe, a4.y, acc[4*i+1]);
                acc[4*i+2] = fmaf(pe, a4.z, acc[4*i+2]);
                acc[4*i+3] = fmaf(pe, a4.w, acc[4*i+3]);
                acc[4*i+0] = fmaf(po, b4.x, acc[4*i+0]);
                acc[4*i+1] = fmaf(po, b4.y, acc[4*i+1]);
                acc[4*i+2] = fmaf(po, b4.z, acc[4*i+2]);
                acc[4*i+3] = fmaf(po, b4.w, acc[4*i+3]);
            }
        }
    }

    float inv = 1.0f / lrow;
    float* outp = g_att + ((size_t)b * TT + trow) * CC + h * 64;
    #pragma unroll
    for (int i = 0; i < 8; i++) {
        float4 o4 = make_float4(acc[4*i+0] * inv, acc[4*i+1] * inv,
                                acc[4*i+2] * inv, acc[4*i+3] * inv);
        *reinterpret_cast<float4*>(&outp[(2 * i + half) * 4]) = o4;
    }
}

// ---------------------------------------------------------------------------
extern "C" void kernel_launch(void* const* d_in, const int* in_sizes, int n_in,
                              void* d_out, int out_size)
{
    const float* x  = (const float*)d_in[0];
    const float* Wq = (const float*)d_in[1];
    const float* Wk = (const float*)d_in[2];
    const float* Wv = (const float*)d_in[3];
    const float* Wp = (const float*)d_in[4];
    const float* bp = (const float*)d_in[5];
    float* out = (float*)d_out;

    prep_w<<<dim3(12, 12, 3), 256>>>(Wq, Wk, Wv);
    gemm_mma<<<dim3(NQKV / BN, BT / BM), 256>>>(x, nullptr, nullptr, nullptr, NQKV, 0);
    attn_kernel<<<dim3(TT / 64, BB * HH), 128>>>();
    gemm_mma<<<dim3(CC / BN, BT / BM), 256>>>(nullptr, Wp, out, bp, CC, 1);
}

// round 16
// speedup vs baseline: 3.1218x; 1.3831x over previous
#include <cuda_runtime.h>
#include <cstdint>

#define BB 8
#define TT 1024
#define CC 768
#define HH 12
#define HS 64
#define BT (BB*TT)
#define NQKV (3*CC)

// GEMM tiling
#define BM 128
#define BN 128
#define BK 16
#define LDT 36     // gemm smem pitch (rows hold BK=16): banks (4g+t)%32 distinct

// Attention smem pitches (rows hold 64 values!)
#define LDQ 68     // 68%32=4  -> A/B frag banks (4g+t)%32 all distinct
#define LDV 72     // 72%32=8  -> V B-frag banks (8t+g)%32 all distinct
#define ATT_SMEM ((3*64*LDQ + 64*LDV) * 4)   // 70656 bytes

// Scratch (allocation-free rule: __device__ globals)
__device__ float g_qkv[(size_t)BT*NQKV];   // [m][n], n = which*768 + h*64 + d
__device__ float g_Bw[(size_t)NQKV*CC];    // K-major transposed QKV weights [n][k]
__device__ float g_att[(size_t)BT*CC];

__device__ __forceinline__ uint32_t f2tf(float f){
    uint32_t r; asm("cvt.rna.tf32.f32 %0, %1;" : "=r"(r) : "f"(f)); return r;
}
__device__ __forceinline__ float uif(uint32_t u){ return __uint_as_float(u); }

__device__ __forceinline__ void mma_tf32(float* d, const uint32_t* a, const uint32_t* b){
    asm volatile(
        "mma.sync.aligned.m16n8k8.row.col.f32.tf32.tf32.f32 "
        "{%0,%1,%2,%3}, {%4,%5,%6,%7}, {%8,%9}, {%0,%1,%2,%3};"
        : "+f"(d[0]), "+f"(d[1]), "+f"(d[2]), "+f"(d[3])
        : "r"(a[0]), "r"(a[1]), "r"(a[2]), "r"(a[3]), "r"(b[0]), "r"(b[1]));
}

// ---------------------------------------------------------------------------
// Kernel 0: tiled transpose of QKV weights into K-major g_Bw[n][k].
// ---------------------------------------------------------------------------
__global__ __launch_bounds__(256) void prep_w(const float* __restrict__ Wq,
                                              const float* __restrict__ Wk,
                                              const float* __restrict__ Wv)
{
    __shared__ float Ts[64][65];
    const int kt = blockIdx.x, h = blockIdx.y, which = blockIdx.z;
    const int tid = threadIdx.x;
    const float* W = (which == 0 ? Wq : (which == 1 ? Wk : Wv));

    #pragma unroll
    for (int i = 0; i < 16; i++) {
        int idx = tid + i * 256;
        int kk = idx >> 6, d = idx & 63;
        Ts[kk][d] = W[((size_t)h * CC + kt * 64 + kk) * HS + d];
    }
    __syncthreads();
    #pragma unroll
    for (int i = 0; i < 16; i++) {
        int idx = tid + i * 256;
        int d = idx >> 6, kk = idx & 63;
        g_Bw[((size_t)which * CC + h * 64 + d) * CC + kt * 64 + kk] = Ts[kk][d];
    }
}

// ---------------------------------------------------------------------------
// Kernels 1+3: tf32 mma.sync GEMM  D[M][N] = A[M][768] * B[N][768]^T (+bias)
// (unchanged from R11 — passed at 107us / 29.5% tensor)
// ---------------------------------------------------------------------------
__global__ __launch_bounds__(256) void gemm_mma(
    const float* __restrict__ Aext,
    const float* __restrict__ Bext,
    float* __restrict__ outext,
    const float* __restrict__ bias,
    int ldc, int mode)
{
    __shared__ uint32_t As[BM * LDT];
    __shared__ uint32_t Bs[BN * LDT];

    const float* A   = mode ? g_att : Aext;
    const float* Bm  = mode ? Bext  : g_Bw;
    float*       out = mode ? outext : g_qkv;

    const int tid  = threadIdx.x;
    const int wid  = tid >> 5, lane = tid & 31;
    const int g    = lane >> 2, t = lane & 3;
    const int wm   = wid & 1;
    const int wn   = wid >> 1;
    const int rowBase = blockIdx.y * BM;
    const int colBase = blockIdx.x * BN;

    const int sm = tid >> 2;
    const int sk = (tid & 3) * 4;

    float acc[4][4][4];
    #pragma unroll
    for (int i = 0; i < 4; i++)
        #pragma unroll
        for (int j = 0; j < 4; j++)
            #pragma unroll
            for (int c = 0; c < 4; c++) acc[i][j][c] = 0.f;

    for (int k0 = 0; k0 < CC; k0 += BK) {
        uint4 ar[2], br[2];
        #pragma unroll
        for (int i = 0; i < 2; i++) {
            float4 av = *reinterpret_cast<const float4*>(
                &A[(size_t)(rowBase + sm + i * 64) * CC + k0 + sk]);
            float4 bv = *reinterpret_cast<const float4*>(
                &Bm[(size_t)(colBase + sm + i * 64) * CC + k0 + sk]);
            ar[i] = make_uint4(f2tf(av.x), f2tf(av.y), f2tf(av.z), f2tf(av.w));
            br[i] = make_uint4(f2tf(bv.x), f2tf(bv.y), f2tf(bv.z), f2tf(bv.w));
        }
        __syncthreads();
        #pragma unroll
        for (int i = 0; i < 2; i++) {
            *reinterpret_cast<uint4*>(&As[(sm + i * 64) * LDT + sk]) = ar[i];
            *reinterpret_cast<uint4*>(&Bs[(sm + i * 64) * LDT + sk]) = br[i];
        }
        __syncthreads();

        #pragma unroll
        for (int kk = 0; kk < BK; kk += 8) {
            uint32_t af[4][4], bf[4][2];
            #pragma unroll
            for (int mi = 0; mi < 4; mi++) {
                const uint32_t* p = &As[(wm * 64 + mi * 16 + g) * LDT + kk + t];
                af[mi][0] = p[0];
                af[mi][1] = p[8 * LDT];
                af[mi][2] = p[4];
                af[mi][3] = p[8 * LDT + 4];
            }
            #pragma unroll
            for (int ni = 0; ni < 4; ni++) {
                const uint32_t* p = &Bs[(wn * 32 + ni * 8 + g) * LDT + kk + t];
                bf[ni][0] = p[0];
                bf[ni][1] = p[4];
            }
            #pragma unroll
            for (int mi = 0; mi < 4; mi++)
                #pragma unroll
                for (int ni = 0; ni < 4; ni++)
                    mma_tf32(acc[mi][ni], af[mi], bf[ni]);
        }
    }

    #pragma unroll
    for (int mi = 0; mi < 4; mi++) {
        int r0 = rowBase + wm * 64 + mi * 16 + g;
        #pragma unroll
        for (int ni = 0; ni < 4; ni++) {
            int c = colBase + wn * 32 + ni * 8 + 2 * t;
            float b0 = 0.f, b1 = 0.f;
            if (bias) { b0 = bias[c]; b1 = bias[c + 1]; }
            float2 lo = make_float2(acc[mi][ni][0] + b0, acc[mi][ni][1] + b1);
            float2 hi = make_float2(acc[mi][ni][2] + b0, acc[mi][ni][3] + b1);
            *reinterpret_cast<float2*>(&out[(size_t)r0 * ldc + c])       = lo;
            *reinterpret_cast<float2*>(&out[(size_t)(r0 + 8) * ldc + c]) = hi;
        }
    }
}

// ---------------------------------------------------------------------------
// Kernel 2: causal flash attention on tensor cores, tf32x2 compensated.
// Block = 4 warps = 64 q rows; K/V tiles 64. Dynamic smem (69KB):
//   Qs[64][LDQ], Ks[64][LDQ], Ps[64][LDQ] (pitch 68: rows hold 64, banks
//   (4g+t)%32 distinct), Vs[64][LDV] (pitch 72: banks (8t+g)%32 distinct).
// S = Qh*Kh + Qh*Kl + Ql*Kh ; O += Ph*Vh + Ph*Vl + Pl*Vh.
// ---------------------------------------------------------------------------
__global__ __launch_bounds__(128) void attn_mma()
{
    extern __shared__ float smx[];
    float* Qs = smx;                 // 64*LDQ
    float* Ks = smx + 64 * LDQ;      // 64*LDQ
    float* Ps = smx + 2 * 64 * LDQ;  // 64*LDQ
    float* Vs = smx + 3 * 64 * LDQ;  // 64*LDV

    const int tid  = threadIdx.x;
    const int wid  = tid >> 5, lane = tid & 31;
    const int g = lane >> 2, t = lane & 3;
    const int qt = blockIdx.x, bh = blockIdx.y;
    const int b = bh / HH, h = bh % HH;
    const size_t m0g = (size_t)b * TT;
    const int m0 = wid * 16;               // warp's q-row base within tile

    // stage Q once (pre-scaled)
    {
        const float* Qg = g_qkv + (m0g + (size_t)qt * 64) * NQKV + h * HS;
        #pragma unroll
        for (int i = 0; i < 8; i++) {
            int idx = tid + i * 128, rr = idx >> 4, d4 = idx & 15;
            float4 v = *reinterpret_cast<const float4*>(Qg + (size_t)rr * NQKV + d4 * 4);
            v.x *= 0.125f; v.y *= 0.125f; v.z *= 0.125f; v.w *= 0.125f;
            *reinterpret_cast<float4*>(&Qs[rr * LDQ + d4 * 4]) = v;
        }
    }
    __syncthreads();

    float mr0 = -1e30f, mr1 = -1e30f, l0 = 0.f, l1 = 0.f;
    float oacc[8][4];
    #pragma unroll
    for (int ni = 0; ni < 8; ni++)
        #pragma unroll
        for (int c = 0; c < 4; c++) oacc[ni][c] = 0.f;

    for (int kt = 0; kt <= qt; kt++) {
        __syncthreads();   // prev iter's K/V readers done
        {
            const float* Kg = g_qkv + (m0g + (size_t)kt * 64) * NQKV + CC + h * HS;
            const float* Vg = g_qkv + (m0g + (size_t)kt * 64) * NQKV + 2 * CC + h * HS;
            #pragma unroll
            for (int i = 0; i < 8; i++) {
                int idx = tid + i * 128, rr = idx >> 4, d4 = idx & 15;
                float4 kv = *reinterpret_cast<const float4*>(Kg + (size_t)rr * NQKV + d4 * 4);
                float4 vv = *reinterpret_cast<const float4*>(Vg + (size_t)rr * NQKV + d4 * 4);
                *reinterpret_cast<float4*>(&Ks[rr * LDQ + d4 * 4]) = kv;
                *reinterpret_cast<float4*>(&Vs[rr * LDV + d4 * 4]) = vv;
            }
        }
        __syncthreads();

        // ---- S = Q K^T (tf32x2 compensated) ----
        float sacc[8][4];
        #pragma unroll
        for (int ni = 0; ni < 8; ni++)
            #pragma unroll
            for (int c = 0; c < 4; c++) sacc[ni][c] = 0.f;

        #pragma unroll
        for (int kk = 0; kk < 64; kk += 8) {
            int ra = (m0 + g) * LDQ + kk + t;
            float a0 = Qs[ra], a1 = Qs[ra + 8 * LDQ], a2 = Qs[ra + 4], a3 = Qs[ra + 8 * LDQ + 4];
            uint32_t ah[4] = { f2tf(a0), f2tf(a1), f2tf(a2), f2tf(a3) };
            uint32_t al[4] = { f2tf(a0 - uif(ah[0])), f2tf(a1 - uif(ah[1])),
                               f2tf(a2 - uif(ah[2])), f2tf(a3 - uif(ah[3])) };
            #pragma unroll
            for (int ni = 0; ni < 8; ni++) {
                int rb = (ni * 8 + g) * LDQ + kk + t;
                float b0 = Ks[rb], b1 = Ks[rb + 4];
                uint32_t bhh[2] = { f2tf(b0), f2tf(b1) };
                uint32_t bll[2] = { f2tf(b0 - uif(bhh[0])), f2tf(b1 - uif(bhh[1])) };
                mma_tf32(sacc[ni], ah, bhh);
                mma_tf32(sacc[ni], ah, bll);
                mma_tf32(sacc[ni], al, bhh);
            }
        }

        // ---- causal mask on the diagonal tile ----
        if (kt == qt) {
            int row0 = m0 + g, row1 = row0 + 8;
            #pragma unroll
            for (int ni = 0; ni < 8; ni++) {
                int c0 = ni * 8 + 2 * t, c1 = c0 + 1;
                if (c0 > row0) sacc[ni][0] = -1e30f;
                if (c1 > row0) sacc[ni][1] = -1e30f;
                if (c0 > row1) sacc[ni][2] = -1e30f;
                if (c1 > row1) sacc[ni][3] = -1e30f;
            }
        }

        // ---- online softmax (rows g and g+8) ----
        float tm0 = -1e30f, tm1 = -1e30f;
        #pragma unroll
        for (int ni = 0; ni < 8; ni++) {
            tm0 = fmaxf(tm0, fmaxf(sacc[ni][0], sacc[ni][1]));
            tm1 = fmaxf(tm1, fmaxf(sacc[ni][2], sacc[ni][3]));
        }
        tm0 = fmaxf(tm0, __shfl_xor_sync(0xffffffffu, tm0, 1));
        tm0 = fmaxf(tm0, __shfl_xor_sync(0xffffffffu, tm0, 2));
        tm1 = fmaxf(tm1, __shfl_xor_sync(0xffffffffu, tm1, 1));
        tm1 = fmaxf(tm1, __shfl_xor_sync(0xffffffffu, tm1, 2));

        float mn0 = fmaxf(mr0, tm0), mn1 = fmaxf(mr1, tm1);
        float cr0 = __expf(mr0 - mn0), cr1 = __expf(mr1 - mn1);
        float ls0 = 0.f, ls1 = 0.f;
        #pragma unroll
        for (int ni = 0; ni < 8; ni++) {
            float p0 = __expf(sacc[ni][0] - mn0);
            float p1 = __expf(sacc[ni][1] - mn0);
            float p2 = __expf(sacc[ni][2] - mn1);
            float p3 = __expf(sacc[ni][3] - mn1);
            ls0 += p0 + p1; ls1 += p2 + p3;
            *reinterpret_cast<float2*>(&Ps[(m0 + g) * LDQ + ni * 8 + 2 * t])     = make_float2(p0, p1);
            *reinterpret_cast<float2*>(&Ps[(m0 + g + 8) * LDQ + ni * 8 + 2 * t]) = make_float2(p2, p3);
        }
        ls0 += __shfl_xor_sync(0xffffffffu, ls0, 1);
        ls0 += __shfl_xor_sync(0xffffffffu, ls0, 2);
        ls1 += __shfl_xor_sync(0xffffffffu, ls1, 1);
        ls1 += __shfl_xor_sync(0xffffffffu, ls1, 2);
        l0 = l0 * cr0 + ls0;
        l1 = l1 * cr1 + ls1;
        mr0 = mn0; mr1 = mn1;
        #pragma unroll
        for (int ni = 0; ni < 8; ni++) {
            oacc[ni][0] *= cr0; oacc[ni][1] *= cr0;
            oacc[ni][2] *= cr1; oacc[ni][3] *= cr1;
        }
        __syncwarp();   // P rows are warp-private; warp-level visibility enough

        // ---- O += P V (tf32x2 compensated) ----
        #pragma unroll
        for (int kk = 0; kk < 64; kk += 8) {
            int ra = (m0 + g) * LDQ + kk + t;
            float a0 = Ps[ra], a1 = Ps[ra + 8 * LDQ], a2 = Ps[ra + 4], a3 = Ps[ra + 8 * LDQ + 4];
            uint32_t ah[4] = { f2tf(a0), f2tf(a1), f2tf(a2), f2tf(a3) };
            uint32_t al[4] = { f2tf(a0 - uif(ah[0])), f2tf(a1 - uif(ah[1])),
                               f2tf(a2 - uif(ah[2])), f2tf(a3 - uif(ah[3])) };
            #pragma unroll
            for (int ni = 0; ni < 8; ni++) {
                int rb = (kk + t) * LDV + ni * 8 + g;
                float b0 = Vs[rb], b1 = Vs[rb + 4 * LDV];
                uint32_t bhh[2] = { f2tf(b0), f2tf(b1) };
                uint32_t bll[2] = { f2tf(b0 - uif(bhh[0])), f2tf(b1 - uif(bhh[1])) };
                mma_tf32(oacc[ni], ah, bhh);
                mma_tf32(oacc[ni], ah, bll);
                mma_tf32(oacc[ni], al, bhh);
            }
        }
    }

    // ---- epilogue ----
    float inv0 = 1.0f / l0, inv1 = 1.0f / l1;
    int r0 = qt * 64 + m0 + g;
    float* outp = g_att + (m0g + r0) * CC + h * 64;
    #pragma unroll
    for (int ni = 0; ni < 8; ni++) {
        int c = ni * 8 + 2 * t;
        *reinterpret_cast<float2*>(&outp[c]) =
            make_float2(oacc[ni][0] * inv0, oacc[ni][1] * inv0);
        *reinterpret_cast<float2*>(&outp[8 * CC + c]) =
            make_float2(oacc[ni][2] * inv1, oacc[ni][3] * inv1);
    }
}

// ---------------------------------------------------------------------------
extern "C" void kernel_launch(void* const* d_in, const int* in_sizes, int n_in,
                              void* d_out, int out_size)
{
    const float* x  = (const float*)d_in[0];
    const float* Wq = (const float*)d_in[1];
    const float* Wk = (const float*)d_in[2];
    const float* Wv = (const float*)d_in[3];
    const float* Wp = (const float*)d_in[4];
    const float* bp = (const float*)d_in[5];
    float* out = (float*)d_out;

    cudaFuncSetAttribute(attn_mma, cudaFuncAttributeMaxDynamicSharedMemorySize, ATT_SMEM);

    prep_w<<<dim3(12, 12, 3), 256>>>(Wq, Wk, Wv);
    gemm_mma<<<dim3(NQKV / BN, BT / BM), 256>>>(x, nullptr, nullptr, nullptr, NQKV, 0);
    attn_mma<<<dim3(TT / 64, BB * HH), 128, ATT_SMEM>>>();
    gemm_mma<<<dim3(CC / BN, BT / BM), 256>>>(nullptr, Wp, out, bp, CC, 1);
}

// round 17
// speedup vs baseline: 3.7439x; 1.1993x over previous
#include <cuda_runtime.h>
#include <cstdint>

#define BB 8
#define TT 1024
#define CC 768
#define HH 12
#define HS 64
#define BT (BB*TT)
#define NQKV (3*CC)

// GEMM tiling
#define BM 128
#define BN 128
#define BK 16
#define LDT 36     // gemm smem pitch (rows hold BK=16): banks (4g+t)%32 distinct

// Attention smem pitches (rows hold 64 values)
#define LDQ 68     // 68%32=4  -> frag banks (4g+t)%32 all distinct
#define LDV 72     // 72%32=8  -> V B-frag banks (8t+g)%32 all distinct
// tiles: Qh, Kh, Kl, Ph (64xLDQ) + Vh, Vl (64xLDV)
#define ATT_SMEM ((4*64*LDQ + 2*64*LDV) * 4)   // 106496 bytes

// Scratch (allocation-free rule: __device__ globals)
__device__ float g_qkv[(size_t)BT*NQKV];   // [m][n], n = which*768 + h*64 + d
__device__ float g_Bw[(size_t)NQKV*CC];    // K-major transposed QKV weights [n][k]
__device__ float g_att[(size_t)BT*CC];

__device__ __forceinline__ uint32_t f2tf(float f){
    uint32_t r; asm("cvt.rna.tf32.f32 %0, %1;" : "=r"(r) : "f"(f)); return r;
}
__device__ __forceinline__ float uif(uint32_t u){ return __uint_as_float(u); }

__device__ __forceinline__ void mma_tf32(float* d, const uint32_t* a, const uint32_t* b){
    asm volatile(
        "mma.sync.aligned.m16n8k8.row.col.f32.tf32.tf32.f32 "
        "{%0,%1,%2,%3}, {%4,%5,%6,%7}, {%8,%9}, {%0,%1,%2,%3};"
        : "+f"(d[0]), "+f"(d[1]), "+f"(d[2]), "+f"(d[3])
        : "r"(a[0]), "r"(a[1]), "r"(a[2]), "r"(a[3]), "r"(b[0]), "r"(b[1]));
}

// ---------------------------------------------------------------------------
// Kernel 0: tiled transpose of QKV weights into K-major g_Bw[n][k].
// ---------------------------------------------------------------------------
__global__ __launch_bounds__(256) void prep_w(const float* __restrict__ Wq,
                                              const float* __restrict__ Wk,
                                              const float* __restrict__ Wv)
{
    __shared__ float Ts[64][65];
    const int kt = blockIdx.x, h = blockIdx.y, which = blockIdx.z;
    const int tid = threadIdx.x;
    const float* W = (which == 0 ? Wq : (which == 1 ? Wk : Wv));

    #pragma unroll
    for (int i = 0; i < 16; i++) {
        int idx = tid + i * 256;
        int kk = idx >> 6, d = idx & 63;
        Ts[kk][d] = W[((size_t)h * CC + kt * 64 + kk) * HS + d];
    }
    __syncthreads();
    #pragma unroll
    for (int i = 0; i < 16; i++) {
        int idx = tid + i * 256;
        int d = idx >> 6, kk = idx & 63;
        g_Bw[((size_t)which * CC + h * 64 + d) * CC + kt * 64 + kk] = Ts[kk][d];
    }
}

// ---------------------------------------------------------------------------
// Kernels 1+3: tf32 mma.sync GEMM  D[M][N] = A[M][768] * B[N][768]^T (+bias)
// (unchanged — 108us / 29.3% tensor)
// ---------------------------------------------------------------------------
__global__ __launch_bounds__(256) void gemm_mma(
    const float* __restrict__ Aext,
    const float* __restrict__ Bext,
    float* __restrict__ outext,
    const float* __restrict__ bias,
    int ldc, int mode)
{
    __shared__ uint32_t As[BM * LDT];
    __shared__ uint32_t Bs[BN * LDT];

    const float* A   = mode ? g_att : Aext;
    const float* Bm  = mode ? Bext  : g_Bw;
    float*       out = mode ? outext : g_qkv;

    const int tid  = threadIdx.x;
    const int wid  = tid >> 5, lane = tid & 31;
    const int g    = lane >> 2, t = lane & 3;
    const int wm   = wid & 1;
    const int wn   = wid >> 1;
    const int rowBase = blockIdx.y * BM;
    const int colBase = blockIdx.x * BN;

    const int sm = tid >> 2;
    const int sk = (tid & 3) * 4;

    float acc[4][4][4];
    #pragma unroll
    for (int i = 0; i < 4; i++)
        #pragma unroll
        for (int j = 0; j < 4; j++)
            #pragma unroll
            for (int c = 0; c < 4; c++) acc[i][j][c] = 0.f;

    for (int k0 = 0; k0 < CC; k0 += BK) {
        uint4 ar[2], br[2];
        #pragma unroll
        for (int i = 0; i < 2; i++) {
            float4 av = *reinterpret_cast<const float4*>(
                &A[(size_t)(rowBase + sm + i * 64) * CC + k0 + sk]);
            float4 bv = *reinterpret_cast<const float4*>(
                &Bm[(size_t)(colBase + sm + i * 64) * CC + k0 + sk]);
            ar[i] = make_uint4(f2tf(av.x), f2tf(av.y), f2tf(av.z), f2tf(av.w));
            br[i] = make_uint4(f2tf(bv.x), f2tf(bv.y), f2tf(bv.z), f2tf(bv.w));
        }
        __syncthreads();
        #pragma unroll
        for (int i = 0; i < 2; i++) {
            *reinterpret_cast<uint4*>(&As[(sm + i * 64) * LDT + sk]) = ar[i];
            *reinterpret_cast<uint4*>(&Bs[(sm + i * 64) * LDT + sk]) = br[i];
        }
        __syncthreads();

        #pragma unroll
        for (int kk = 0; kk < BK; kk += 8) {
            uint32_t af[4][4], bf[4][2];
            #pragma unroll
            for (int mi = 0; mi < 4; mi++) {
                const uint32_t* p = &As[(wm * 64 + mi * 16 + g) * LDT + kk + t];
                af[mi][0] = p[0];
                af[mi][1] = p[8 * LDT];
                af[mi][2] = p[4];
                af[mi][3] = p[8 * LDT + 4];
            }
            #pragma unroll
            for (int ni = 0; ni < 4; ni++) {
                const uint32_t* p = &Bs[(wn * 32 + ni * 8 + g) * LDT + kk + t];
                bf[ni][0] = p[0];
                bf[ni][1] = p[4];
            }
            #pragma unroll
            for (int mi = 0; mi < 4; mi++)
                #pragma unroll
                for (int ni = 0; ni < 4; ni++)
                    mma_tf32(acc[mi][ni], af[mi], bf[ni]);
        }
    }

    #pragma unroll
    for (int mi = 0; mi < 4; mi++) {
        int r0 = rowBase + wm * 64 + mi * 16 + g;
        #pragma unroll
        for (int ni = 0; ni < 4; ni++) {
            int c = colBase + wn * 32 + ni * 8 + 2 * t;
            float b0 = 0.f, b1 = 0.f;
            if (bias) { b0 = bias[c]; b1 = bias[c + 1]; }
            float2 lo = make_float2(acc[mi][ni][0] + b0, acc[mi][ni][1] + b1);
            float2 hi = make_float2(acc[mi][ni][2] + b0, acc[mi][ni][3] + b1);
            *reinterpret_cast<float2*>(&out[(size_t)r0 * ldc + c])       = lo;
            *reinterpret_cast<float2*>(&out[(size_t)(r0 + 8) * ldc + c]) = hi;
        }
    }
}

// ---------------------------------------------------------------------------
// Kernel 2: causal flash attention on tensor cores, tf32 compensated with
// pre-rounded hi/lo SMEM tiles (zero cvt in the MMA loops).
//   S = Qh*Kh + Qh*Kl + Ql*Kh   (Ql loop-invariant in registers)
//   O += Ph*Vh + Ph*Vl          (Pl term dropped: ~2.4e-4 contribution)
// Tiles store tf32-rounded floats; fragments are raw-bit LDS.
// ---------------------------------------------------------------------------
__global__ __launch_bounds__(128) void attn_mma()
{
    extern __shared__ float smx[];
    float* Qh = smx;                              // 64*LDQ (rounded, scaled)
    float* Kh = smx + 64 * LDQ;                   // 64*LDQ
    float* Kl = smx + 2 * 64 * LDQ;               // 64*LDQ
    float* Ph = smx + 3 * 64 * LDQ;               // 64*LDQ
    float* Vh = smx + 4 * 64 * LDQ;               // 64*LDV
    float* Vl = smx + 4 * 64 * LDQ + 64 * LDV;    // 64*LDV

    const int tid  = threadIdx.x;
    const int wid  = tid >> 5, lane = tid & 31;
    const int g = lane >> 2, t = lane & 3;
    const int qt = blockIdx.x, bh = blockIdx.y;
    const int b = bh / HH, h = bh % HH;
    const size_t m0g = (size_t)b * TT;
    const int m0 = wid * 16;               // warp's q-row base within tile

    // ---- stage Q (scaled, full precision) into Qh ----
    {
        const float* Qg = g_qkv + (m0g + (size_t)qt * 64) * NQKV + h * HS;
        #pragma unroll
        for (int i = 0; i < 8; i++) {
            int idx = tid + i * 128, rr = idx >> 4, d4 = idx & 15;
            float4 v = *reinterpret_cast<const float4*>(Qg + (size_t)rr * NQKV + d4 * 4);
            v.x *= 0.125f; v.y *= 0.125f; v.z *= 0.125f; v.w *= 0.125f;
            *reinterpret_cast<float4*>(&Qh[rr * LDQ + d4 * 4]) = v;
        }
    }
    __syncthreads();

    // ---- split Q: round Qh in place, keep residual fragments in registers.
    // Fragment addresses are thread-private (same thread reads them in the
    // S-loop), so in-place rewrite is hazard-free.
    uint32_t ql[8][4];
    #pragma unroll
    for (int k8 = 0; k8 < 8; k8++) {
        int ra = (m0 + g) * LDQ + k8 * 8 + t;
        float a0 = Qh[ra], a1 = Qh[ra + 8 * LDQ], a2 = Qh[ra + 4], a3 = Qh[ra + 8 * LDQ + 4];
        uint32_t h0 = f2tf(a0), h1 = f2tf(a1), h2 = f2tf(a2), h3 = f2tf(a3);
        ql[k8][0] = f2tf(a0 - uif(h0));
        ql[k8][1] = f2tf(a1 - uif(h1));
        ql[k8][2] = f2tf(a2 - uif(h2));
        ql[k8][3] = f2tf(a3 - uif(h3));
        Qh[ra] = uif(h0); Qh[ra + 8 * LDQ] = uif(h1);
        Qh[ra + 4] = uif(h2); Qh[ra + 8 * LDQ + 4] = uif(h3);
    }

    float mr0 = -1e30f, mr1 = -1e30f, l0 = 0.f, l1 = 0.f;
    float oacc[8][4];
    #pragma unroll
    for (int ni = 0; ni < 8; ni++)
        #pragma unroll
        for (int c = 0; c < 4; c++) oacc[ni][c] = 0.f;

    for (int kt = 0; kt <= qt; kt++) {
        __syncthreads();   // prev iter's Kh/Kl/Vh/Vl readers done
        {
            const float* Kg = g_qkv + (m0g + (size_t)kt * 64) * NQKV + CC + h * HS;
            const float* Vg = g_qkv + (m0g + (size_t)kt * 64) * NQKV + 2 * CC + h * HS;
            #pragma unroll
            for (int i = 0; i < 8; i++) {
                int idx = tid + i * 128, rr = idx >> 4, d4 = idx & 15;
                float4 kv = *reinterpret_cast<const float4*>(Kg + (size_t)rr * NQKV + d4 * 4);
                float4 vv = *reinterpret_cast<const float4*>(Vg + (size_t)rr * NQKV + d4 * 4);
                float4 khv, klv, vhv, vlv;
                khv.x = uif(f2tf(kv.x)); klv.x = uif(f2tf(kv.x - khv.x));
                khv.y = uif(f2tf(kv.y)); klv.y = uif(f2tf(kv.y - khv.y));
                khv.z = uif(f2tf(kv.z)); klv.z = uif(f2tf(kv.z - khv.z));
                khv.w = uif(f2tf(kv.w)); klv.w = uif(f2tf(kv.w - khv.w));
                vhv.x = uif(f2tf(vv.x)); vlv.x = uif(f2tf(vv.x - vhv.x));
                vhv.y = uif(f2tf(vv.y)); vlv.y = uif(f2tf(vv.y - vhv.y));
                vhv.z = uif(f2tf(vv.z)); vlv.z = uif(f2tf(vv.z - vhv.z));
                vhv.w = uif(f2tf(vv.w)); vlv.w = uif(f2tf(vv.w - vhv.w));
                *reinterpret_cast<float4*>(&Kh[rr * LDQ + d4 * 4]) = khv;
                *reinterpret_cast<float4*>(&Kl[rr * LDQ + d4 * 4]) = klv;
                *reinterpret_cast<float4*>(&Vh[rr * LDV + d4 * 4]) = vhv;
                *reinterpret_cast<float4*>(&Vl[rr * LDV + d4 * 4]) = vlv;
            }
        }
        __syncthreads();

        // ---- S = Q K^T ----
        float sacc[8][4];
        #pragma unroll
        for (int ni = 0; ni < 8; ni++)
            #pragma unroll
            for (int c = 0; c < 4; c++) sacc[ni][c] = 0.f;

        #pragma unroll
        for (int k8 = 0; k8 < 8; k8++) {
            int kk = k8 * 8;
            int ra = (m0 + g) * LDQ + kk + t;
            uint32_t ah[4] = { __float_as_uint(Qh[ra]),
                               __float_as_uint(Qh[ra + 8 * LDQ]),
                               __float_as_uint(Qh[ra + 4]),
                               __float_as_uint(Qh[ra + 8 * LDQ + 4]) };
            #pragma unroll
            for (int ni = 0; ni < 8; ni++) {
                int rb = (ni * 8 + g) * LDQ + kk + t;
                uint32_t bhh[2] = { __float_as_uint(Kh[rb]), __float_as_uint(Kh[rb + 4]) };
                uint32_t bll[2] = { __float_as_uint(Kl[rb]), __float_as_uint(Kl[rb + 4]) };
                mma_tf32(sacc[ni], ah, bhh);
                mma_tf32(sacc[ni], ah, bll);
                mma_tf32(sacc[ni], ql[k8], bhh);
            }
        }

        // ---- causal mask on the diagonal tile ----
        if (kt == qt) {
            int row0 = m0 + g, row1 = row0 + 8;
            #pragma unroll
            for (int ni = 0; ni < 8; ni++) {
                int c0 = ni * 8 + 2 * t, c1 = c0 + 1;
                if (c0 > row0) sacc[ni][0] = -1e30f;
                if (c1 > row0) sacc[ni][1] = -1e30f;
                if (c0 > row1) sacc[ni][2] = -1e30f;
                if (c1 > row1) sacc[ni][3] = -1e30f;
            }
        }

        // ---- online softmax (rows g and g+8); store rounded P ----
        float tm0 = -1e30f, tm1 = -1e30f;
        #pragma unroll
        for (int ni = 0; ni < 8; ni++) {
            tm0 = fmaxf(tm0, fmaxf(sacc[ni][0], sacc[ni][1]));
            tm1 = fmaxf(tm1, fmaxf(sacc[ni][2], sacc[ni][3]));
        }
        tm0 = fmaxf(tm0, __shfl_xor_sync(0xffffffffu, tm0, 1));
        tm0 = fmaxf(tm0, __shfl_xor_sync(0xffffffffu, tm0, 2));
        tm1 = fmaxf(tm1, __shfl_xor_sync(0xffffffffu, tm1, 1));
        tm1 = fmaxf(tm1, __shfl_xor_sync(0xffffffffu, tm1, 2));

        float mn0 = fmaxf(mr0, tm0), mn1 = fmaxf(mr1, tm1);
        float cr0 = __expf(mr0 - mn0), cr1 = __expf(mr1 - mn1);
        float ls0 = 0.f, ls1 = 0.f;
        #pragma unroll
        for (int ni = 0; ni < 8; ni++) {
            float p0 = __expf(sacc[ni][0] - mn0);
            float p1 = __expf(sacc[ni][1] - mn0);
            float p2 = __expf(sacc[ni][2] - mn1);
            float p3 = __expf(sacc[ni][3] - mn1);
            ls0 += p0 + p1; ls1 += p2 + p3;
            *reinterpret_cast<float2*>(&Ph[(m0 + g) * LDQ + ni * 8 + 2 * t]) =
                make_float2(uif(f2tf(p0)), uif(f2tf(p1)));
            *reinterpret_cast<float2*>(&Ph[(m0 + g + 8) * LDQ + ni * 8 + 2 * t]) =
                make_float2(uif(f2tf(p2)), uif(f2tf(p3)));
        }
        ls0 += __shfl_xor_sync(0xffffffffu, ls0, 1);
        ls0 += __shfl_xor_sync(0xffffffffu, ls0, 2);
        ls1 += __shfl_xor_sync(0xffffffffu, ls1, 1);
        ls1 += __shfl_xor_sync(0xffffffffu, ls1, 2);
        l0 = l0 * cr0 + ls0;
        l1 = l1 * cr1 + ls1;
        mr0 = mn0; mr1 = mn1;
        #pragma unroll
        for (int ni = 0; ni < 8; ni++) {
            oacc[ni][0] *= cr0; oacc[ni][1] *= cr0;
            oacc[ni][2] *= cr1; oacc[ni][3] *= cr1;
        }
        __syncwarp();   // Ph rows are warp-private

        // ---- O += P V ----
        #pragma unroll
        for (int k8 = 0; k8 < 8; k8++) {
            int kk = k8 * 8;
            int ra = (m0 + g) * LDQ + kk + t;
            uint32_t ah[4] = { __float_as_uint(Ph[ra]),
                               __float_as_uint(Ph[ra + 8 * LDQ]),
                               __float_as_uint(Ph[ra + 4]),
                               __float_as_uint(Ph[ra + 8 * LDQ + 4]) };
            #pragma unroll
            for (int ni = 0; ni < 8; ni++) {
                int rb = (kk + t) * LDV + ni * 8 + g;
                uint32_t bhh[2] = { __float_as_uint(Vh[rb]), __float_as_uint(Vh[rb + 4 * LDV]) };
                uint32_t bll[2] = { __float_as_uint(Vl[rb]), __float_as_uint(Vl[rb + 4 * LDV]) };
                mma_tf32(oacc[ni], ah, bhh);
                mma_tf32(oacc[ni], ah, bll);
            }
        }
    }

    // ---- epilogue ----
    float inv0 = 1.0f / l0, inv1 = 1.0f / l1;
    int r0 = qt * 64 + m0 + g;
    float* outp = g_att + (m0g + r0) * CC + h * 64;
    #pragma unroll
    for (int ni = 0; ni < 8; ni++) {
        int c = ni * 8 + 2 * t;
        *reinterpret_cast<float2*>(&outp[c]) =
            make_float2(oacc[ni][0] * inv0, oacc[ni][1] * inv0);
        *reinterpret_cast<float2*>(&outp[8 * CC + c]) =
            make_float2(oacc[ni][2] * inv1, oacc[ni][3] * inv1);
    }
}

// ---------------------------------------------------------------------------
extern "C" void kernel_launch(void* const* d_in, const int* in_sizes, int n_in,
                              void* d_out, int out_size)
{
    const float* x  = (const float*)d_in[0];
    const float* Wq = (const float*)d_in[1];
    const float* Wk = (const float*)d_in[2];
    const float* Wv = (const float*)d_in[3];
    const float* Wp = (const float*)d_in[4];
    const float* bp = (const float*)d_in[5];
    float* out = (float*)d_out;

    cudaFuncSetAttribute(attn_mma, cudaFuncAttributeMaxDynamicSharedMemorySize, ATT_SMEM);

    prep_w<<<dim3(12, 12, 3), 256>>>(Wq, Wk, Wv);
    gemm_mma<<<dim3(NQKV / BN, BT / BM), 256>>>(x, nullptr, nullptr, nullptr, NQKV, 0);
    attn_mma<<<dim3(TT / 64, BB * HH), 128, ATT_SMEM>>>();
    gemm_mma<<<dim3(CC / BN, BT / BM), 256>>>(nullptr, Wp, out, bp, CC, 1);
}